// round 6
// baseline (speedup 1.0000x reference)
#include <cuda_runtime.h>
#include <cuda_bf16.h>

// SimSiam loss, algebraically reduced:
//   loss = -0.5 * sum_c( P_c . Z_c  -  sum_{i in c} pn_i.zn_i ) / npairs
// where P_c/Z_c are per-class sums of L2-normalized rows and
// npairs = sum_c m_c*(m_c-1)/2.   O(n*d) work, no 8192x8192 GEMM.
//
// SINGLE-KERNEL design: phase 1 accumulates per-class sums; a software
// grid barrier (arrive counter + spin by blocks 0..63 only) hands off to
// phase 2, where blocks 0..63 compute per-class dots, fold in diag
// partials, and the last-done block emits the loss. All scratch is
// restored to zero before the kernel finishes (launch-entry invariant).
//
// Residency: __launch_bounds__(256, 8) -> 8 CTAs/SM * 148 SMs = 1184 >= 1024
// blocks, one wave. Even without full residency there is no deadlock:
// only blocks 0..63 spin; all other blocks arrive and exit, freeing SMs.

#define NCLASS 512
#define D      128
#define EPS    1e-8f
#define FBLK   64          // number of phase-2 blocks

__device__ float              g_P[NCLASS * D];
__device__ float              g_Z[NCLASS * D];
__device__ int                g_cnt[NCLASS];
__device__ double             g_Dpart[FBLK];   // diag partials (accumulated)
__device__ double             g_S;             // final scalar accumulator
__device__ unsigned long long g_pairs;
__device__ unsigned int       g_arrive;        // grid-barrier arrivals
__device__ unsigned int       g_done;          // phase-2 completion counter

// 128-bit reduction into global memory (sm_90+), no return value.
__device__ __forceinline__ void red_add_v4(float* p, float x, float y, float z, float w) {
    asm volatile("red.global.add.v4.f32 [%0], {%1, %2, %3, %4};"
                 :: "l"(p), "f"(x), "f"(y), "f"(z), "f"(w) : "memory");
}

__global__ void __launch_bounds__(256, 8)
simsiam_kernel(const float* __restrict__ ps,
               const float* __restrict__ zs,
               const void*  __restrict__ tgv,
               float* __restrict__ out,
               int n_rows, unsigned int n_blocks) {
    __shared__ double sdp[8];
    __shared__ int    s_is64;

    int warp_in_blk = threadIdx.x >> 5;
    int lane        = threadIdx.x & 31;
    int warp        = (blockIdx.x * blockDim.x + threadIdx.x) >> 5;

    // ---- targets dtype sniff (warp 0): first 64 int64-view slots (512 B,
    // in-bounds for either dtype). int32 misdetects only if 64 consecutive
    // odd-position labels are all zero (~2^-576 for random labels).
    if (warp_in_blk == 0) {
        const long long* t64 = (const long long*)tgv;
        int nslots = n_rows / 2;
        int k = (nslots < 64) ? nslots : 64;
        int bad = 0;
        for (int i = lane; i < k; i += 32) {
            long long v = __ldg(&t64[i]);
            if (v < 0 || v >= NCLASS) bad = 1;
        }
        bad = __any_sync(0xFFFFFFFFu, bad);
        if (lane == 0) s_is64 = !bad;
    }
    __syncthreads();
    int is64 = s_is64;

    // ---- phase 1: one warp per row ----
    double diag = 0.0;
    if (warp < n_rows) {
        float4 a = reinterpret_cast<const float4*>(ps)[warp * (D / 4) + lane];
        float4 b = reinterpret_cast<const float4*>(zs)[warp * (D / 4) + lane];

        float sa = a.x * a.x + a.y * a.y + a.z * a.z + a.w * a.w;
        float sb = b.x * b.x + b.y * b.y + b.z * b.z + b.w * b.w;
        float dp = a.x * b.x + a.y * b.y + a.z * b.z + a.w * b.w;

        #pragma unroll
        for (int o = 16; o > 0; o >>= 1) {
            sa += __shfl_xor_sync(0xFFFFFFFFu, sa, o);
            sb += __shfl_xor_sync(0xFFFFFFFFu, sb, o);
            dp += __shfl_xor_sync(0xFFFFFFFFu, dp, o);
        }

        float invp = 1.0f / fmaxf(sqrtf(sa), EPS);
        float invz = 1.0f / fmaxf(sqrtf(sb), EPS);

        int t;
        if (is64) t = (int)reinterpret_cast<const long long*>(tgv)[warp];
        else      t = reinterpret_cast<const int*>(tgv)[warp];

        red_add_v4(&g_P[t * D + lane * 4], a.x * invp, a.y * invp, a.z * invp, a.w * invp);
        red_add_v4(&g_Z[t * D + lane * 4], b.x * invz, b.y * invz, b.z * invz, b.w * invz);

        if (lane == 0) {
            atomicAdd(&g_cnt[t], 1);
            diag = (double)(dp * invp * invz);
        }
    }
    if (lane == 0) sdp[warp_in_blk] = diag;
    __syncthreads();
    if (threadIdx.x == 0) {
        double s = sdp[0] + sdp[1] + sdp[2] + sdp[3]
                 + sdp[4] + sdp[5] + sdp[6] + sdp[7];
        atomicAdd(&g_Dpart[blockIdx.x & (FBLK - 1)], s);
    }

    // ---- grid barrier: everyone arrives; only blocks 0..63 wait ----
    __shared__ int s_go;
    if (threadIdx.x == 0) {
        __threadfence();                               // publish phase-1 writes
        unsigned int a = atomicAdd(&g_arrive, 1u) + 1u;
        if (blockIdx.x < FBLK) {
            while (a < n_blocks) {
                __nanosleep(64);
                a = *(volatile unsigned int*)&g_arrive;
            }
            __threadfence();                           // acquire
        }
        s_go = 1;
    }
    __syncthreads();
    (void)s_go;
    if (blockIdx.x >= FBLK) return;

    // ---- phase 2: blocks 0..63, warp per class (8 classes/block) ----
    {
        int wid = warp_in_blk;                 // 0..7
        int c   = blockIdx.x * 8 + wid;
        int idx = c * (D / 4) + lane;

        float4 p = reinterpret_cast<const float4*>(g_P)[idx];
        float4 z = reinterpret_cast<const float4*>(g_Z)[idx];
        float dot = p.x * z.x + p.y * z.y + p.z * z.z + p.w * z.w;
        #pragma unroll
        for (int o = 16; o > 0; o >>= 1)
            dot += __shfl_xor_sync(0xFFFFFFFFu, dot, o);

        unsigned long long m = (unsigned long long)g_cnt[c];
        if (lane == 0) {
            sdp[wid] = (double)dot;            // reuse shared buffer
        }

        // restore launch-entry zero invariant for the slices we own
        float4 zero4 = make_float4(0.f, 0.f, 0.f, 0.f);
        reinterpret_cast<float4*>(g_P)[idx] = zero4;
        reinterpret_cast<float4*>(g_Z)[idx] = zero4;
        if (lane == 0) g_cnt[c] = 0;

        __shared__ unsigned long long spair[8];
        if (lane == 0) spair[wid] = m * (m - 1ull) / 2ull;
        __syncthreads();

        if (threadIdx.x == 0) {
            double s = sdp[0] + sdp[1] + sdp[2] + sdp[3]
                     + sdp[4] + sdp[5] + sdp[6] + sdp[7]
                     - g_Dpart[blockIdx.x];            // fold diag partial
            g_Dpart[blockIdx.x] = 0.0;                 // re-zero scratch
            unsigned long long pr = spair[0] + spair[1] + spair[2] + spair[3]
                                  + spair[4] + spair[5] + spair[6] + spair[7];
            atomicAdd(&g_S, s);                        // 64 atomics total
            if (pr) atomicAdd(&g_pairs, pr);
            __threadfence();
            unsigned int done = atomicAdd(&g_done, 1u);
            if (done == (unsigned int)(FBLK - 1)) {
                double np = (g_pairs > 0ull) ? (double)g_pairs : 1.0;
                out[0] = (float)(-0.5 * g_S / np);
                g_S = 0.0; g_pairs = 0ull;
                g_arrive = 0u; g_done = 0u;
            }
        }
    }
}

// ---------------------------------------------------------------------------
extern "C" void kernel_launch(void* const* d_in, const int* in_sizes, int n_in,
                              void* d_out, int out_size) {
    const float* ps  = (const float*)d_in[0];
    const float* zs  = (const float*)d_in[1];
    const void*  tgt = d_in[2];
    float*       out = (float*)d_out;

    int n_rows = in_sizes[0] / D;               // 8192
    unsigned int n_blocks = (n_rows + 7) / 8;   // 1024

    simsiam_kernel<<<n_blocks, 256>>>(ps, zs, tgt, out, n_rows, n_blocks);
}

// round 7
// speedup vs baseline: 1.1629x; 1.1629x over previous
#include <cuda_runtime.h>
#include <cuda_bf16.h>

// SimSiam loss, algebraically reduced:
//   loss = -0.5 * sum_c( P_c . Z_c  -  sum_{i in c} pn_i.zn_i ) / npairs
// where P_c/Z_c are per-class sums of L2-normalized rows and
// npairs = sum_c m_c*(m_c-1)/2.   O(n*d) work, no 8192x8192 GEMM.
//
// Two kernels (fused single-kernel variant measured SLOWER due to grid-
// barrier straggler wait). final_kernel does ONE double atomic per block
// (64 total) — round 4's 512 single-address atomics were its bottleneck;
// round 5's fence-heavy plain-store scheme was worse still.
//
// Scratch invariant: all accumulated __device__ scratch is ZERO at
// kernel_launch entry (zero at module load; final_kernel re-zeros before
// finishing).

#define NCLASS 512
#define D      128
#define EPS    1e-8f
#define FBLK   64          // final_kernel grid size

__device__ float              g_P[NCLASS * D];
__device__ float              g_Z[NCLASS * D];
__device__ int                g_cnt[NCLASS];
__device__ double             g_Dpart[FBLK];   // diag partials (accumulated)
__device__ double             g_S;             // final scalar accumulator
__device__ unsigned long long g_pairs;
__device__ unsigned int       g_done;

// 128-bit reduction into global memory (sm_90+), no return value.
__device__ __forceinline__ void red_add_v4(float* p, float x, float y, float z, float w) {
    asm volatile("red.global.add.v4.f32 [%0], {%1, %2, %3, %4};"
                 :: "l"(p), "f"(x), "f"(y), "f"(z), "f"(w) : "memory");
}

// ---------------------------------------------------------------------------
// One warp per row: float4 loads, warp-reduce norms + dot, scatter normalized
// rows into per-class sums with 128-bit vector atomics. In-block dtype sniff:
// warp 0 reads the first 64 int64-view slots (512 B, in-bounds either way);
// an int32 buffer misdetects only if 64 consecutive odd labels are 0.
__global__ void accum_kernel(const float* __restrict__ ps,
                             const float* __restrict__ zs,
                             const void*  __restrict__ tgv,
                             int n_rows) {
    __shared__ double sdp[8];
    __shared__ int    s_is64;

    int warp_in_blk = threadIdx.x >> 5;
    int lane        = threadIdx.x & 31;
    int warp        = (blockIdx.x * blockDim.x + threadIdx.x) >> 5;

    if (warp_in_blk == 0) {
        const long long* t64 = (const long long*)tgv;
        int nslots = n_rows / 2;
        int k = (nslots < 64) ? nslots : 64;
        int bad = 0;
        for (int i = lane; i < k; i += 32) {
            long long v = __ldg(&t64[i]);
            if (v < 0 || v >= NCLASS) bad = 1;
        }
        bad = __any_sync(0xFFFFFFFFu, bad);
        if (lane == 0) s_is64 = !bad;
    }
    __syncthreads();
    int is64 = s_is64;

    double diag = 0.0;
    if (warp < n_rows) {
        float4 a = reinterpret_cast<const float4*>(ps)[warp * (D / 4) + lane];
        float4 b = reinterpret_cast<const float4*>(zs)[warp * (D / 4) + lane];

        float sa = a.x * a.x + a.y * a.y + a.z * a.z + a.w * a.w;
        float sb = b.x * b.x + b.y * b.y + b.z * b.z + b.w * b.w;
        float dp = a.x * b.x + a.y * b.y + a.z * b.z + a.w * b.w;

        #pragma unroll
        for (int o = 16; o > 0; o >>= 1) {
            sa += __shfl_xor_sync(0xFFFFFFFFu, sa, o);
            sb += __shfl_xor_sync(0xFFFFFFFFu, sb, o);
            dp += __shfl_xor_sync(0xFFFFFFFFu, dp, o);
        }

        float invp = 1.0f / fmaxf(sqrtf(sa), EPS);
        float invz = 1.0f / fmaxf(sqrtf(sb), EPS);

        int t;
        if (is64) t = (int)reinterpret_cast<const long long*>(tgv)[warp];
        else      t = reinterpret_cast<const int*>(tgv)[warp];

        red_add_v4(&g_P[t * D + lane * 4], a.x * invp, a.y * invp, a.z * invp, a.w * invp);
        red_add_v4(&g_Z[t * D + lane * 4], b.x * invz, b.y * invz, b.z * invz, b.w * invz);

        if (lane == 0) {
            atomicAdd(&g_cnt[t], 1);
            diag = (double)(dp * invp * invz);
        }
    }
    if (lane == 0) sdp[warp_in_blk] = diag;
    __syncthreads();
    if (threadIdx.x == 0) {
        double s = sdp[0] + sdp[1] + sdp[2] + sdp[3]
                 + sdp[4] + sdp[5] + sdp[6] + sdp[7];
        // spread over 64 slots -> no single-address funnel
        atomicAdd(&g_Dpart[blockIdx.x & (FBLK - 1)], s);
    }
}

// ---------------------------------------------------------------------------
// Per-class dot (warp per class, 8 classes/block) + pair count; block-level
// shared reduce -> ONE double atomic + one u64 atomic per block; fold the
// block's diag partial locally; scratch re-zero; last-block epilogue.
__global__ void final_kernel(float* __restrict__ out) {
    __shared__ double             sdot[8];
    __shared__ unsigned long long spair[8];

    int lane = threadIdx.x & 31;
    int wid  = threadIdx.x >> 5;                 // 0..7
    int c    = blockIdx.x * 8 + wid;
    int idx  = c * (D / 4) + lane;

    float4 p = reinterpret_cast<const float4*>(g_P)[idx];
    float4 z = reinterpret_cast<const float4*>(g_Z)[idx];
    float dot = p.x * z.x + p.y * z.y + p.z * z.z + p.w * z.w;
    #pragma unroll
    for (int o = 16; o > 0; o >>= 1)
        dot += __shfl_xor_sync(0xFFFFFFFFu, dot, o);

    unsigned long long m = (unsigned long long)g_cnt[c];
    if (lane == 0) {
        sdot[wid]  = (double)dot;
        spair[wid] = m * (m - 1ull) / 2ull;
    }

    // Re-zero the slices this block owns (restores launch-entry invariant).
    float4 zero4 = make_float4(0.f, 0.f, 0.f, 0.f);
    reinterpret_cast<float4*>(g_P)[idx] = zero4;
    reinterpret_cast<float4*>(g_Z)[idx] = zero4;
    if (lane == 0) g_cnt[c] = 0;

    __syncthreads();
    if (threadIdx.x == 0) {
        double s = sdot[0] + sdot[1] + sdot[2] + sdot[3]
                 + sdot[4] + sdot[5] + sdot[6] + sdot[7]
                 - g_Dpart[blockIdx.x];              // fold diag partial
        g_Dpart[blockIdx.x] = 0.0;                   // re-zero scratch
        unsigned long long pr = spair[0] + spair[1] + spair[2] + spair[3]
                              + spair[4] + spair[5] + spair[6] + spair[7];
        atomicAdd(&g_S, s);                          // 64 atomics total
        atomicAdd(&g_pairs, pr);
        __threadfence();
        unsigned int done = atomicAdd(&g_done, 1u);
        if (done == (unsigned int)(FBLK - 1)) {
            double np = (g_pairs > 0ull) ? (double)g_pairs : 1.0;
            out[0] = (float)(-0.5 * g_S / np);
            g_S = 0.0; g_pairs = 0ull; g_done = 0u;
        }
    }
}

// ---------------------------------------------------------------------------
extern "C" void kernel_launch(void* const* d_in, const int* in_sizes, int n_in,
                              void* d_out, int out_size) {
    const float* ps  = (const float*)d_in[0];
    const float* zs  = (const float*)d_in[1];
    const void*  tgt = d_in[2];
    float*       out = (float*)d_out;

    int n_rows = in_sizes[0] / D;   // 8192

    accum_kernel<<<(n_rows + 7) / 8, 256>>>(ps, zs, tgt, n_rows);
    final_kernel<<<FBLK, 256>>>(out);
}